// round 1
// baseline (speedup 1.0000x reference)
#include <cuda_runtime.h>
#include <cstdint>

#define BB 8
#define TT 16
#define NN 1024
#define HH 128
#define NHEADS 8
#define HD 16
#define SNP 4
#define NT 4096
#define EMAX 65536
#define LRELU_SLOPE 0.2f
#define MAXDEG 16

// ---------------- scratch (device globals; no allocation allowed) -------------
__device__ float g_x[BB*TT*NN*HH];       // (B,T,N,H)
__device__ float g_fs[BB*SNP*NN*HH];     // (B,4,N,H) segment input / residual
__device__ float g_feat[BB*NT*HH];       // GAT per-layer features (pre-agg)
__device__ float g_h0[BB*NT*HH];         // layer0 output
__device__ float g_h1[BB*NT*HH];         // layer1 output (+residual)
__device__ float g_el[BB*NT*NHEADS];
__device__ float g_er[BB*NT*NHEADS];
__device__ float g_alpha[BB*EMAX*NHEADS];
__device__ float g_last[BB*NN*HH];
__device__ float g_stats[BB*2];          // per-batch sum, sumsq
__device__ int   g_deg[NT];
__device__ int   g_cnt[NT];
__device__ int   g_off[NT+1];
__device__ int   g_eid[EMAX];
__device__ int   g_srcs[EMAX];           // CSR-ordered source node ids

// ---------------- CSR build ---------------------------------------------------
__global__ void k_zero() {
    int i = blockIdx.x*blockDim.x + threadIdx.x;
    if (i < NT) { g_deg[i] = 0; g_cnt[i] = 0; }
}

__global__ void k_count(const int* __restrict__ edst, int E) {
    int i = blockIdx.x*blockDim.x + threadIdx.x;
    if (i < E) atomicAdd(&g_deg[edst[i]], 1);
}

__global__ void k_scan() {   // 1 block, 1024 threads, NT=4096
    __shared__ int sh[1024];
    int tid = threadIdx.x;
    int d0 = g_deg[tid*4+0], d1 = g_deg[tid*4+1], d2 = g_deg[tid*4+2], d3 = g_deg[tid*4+3];
    int tot = d0+d1+d2+d3;
    sh[tid] = tot; __syncthreads();
    for (int o = 1; o < 1024; o <<= 1) {
        int v = (tid >= o) ? sh[tid-o] : 0;
        __syncthreads();
        sh[tid] += v;
        __syncthreads();
    }
    int excl = sh[tid] - tot;
    g_off[tid*4+0] = excl;
    g_off[tid*4+1] = excl + d0;
    g_off[tid*4+2] = excl + d0 + d1;
    g_off[tid*4+3] = excl + d0 + d1 + d2;
    if (tid == 1023) g_off[NT] = sh[1023];
}

__global__ void k_fill(const int* __restrict__ edst, int E) {
    int i = blockIdx.x*blockDim.x + threadIdx.x;
    if (i >= E) return;
    int v = edst[i];
    int slot = g_off[v] + atomicAdd(&g_cnt[v], 1);
    g_eid[slot] = i;
}

// deterministic ordering: sort each node's edge ids (deg <= 10)
__global__ void k_sort(const int* __restrict__ esrc) {
    int v = blockIdx.x*blockDim.x + threadIdx.x;
    if (v >= NT) return;
    int o0 = g_off[v];
    int d = g_deg[v]; if (d > MAXDEG) d = MAXDEG;
    for (int i = 1; i < d; i++) {
        int key = g_eid[o0+i];
        int j = i-1;
        while (j >= 0 && g_eid[o0+j] > key) { g_eid[o0+j+1] = g_eid[o0+j]; j--; }
        g_eid[o0+j+1] = key;
    }
    for (int j = 0; j < d; j++) g_srcs[o0+j] = esrc[g_eid[o0+j]];
}

// ---------------- x = inputs@W_in + b_in + spatial + temporal -----------------
__global__ void k_x(const float* __restrict__ in, const float* __restrict__ Win,
                    const float* __restrict__ bin, const float* __restrict__ spat,
                    const float* __restrict__ temp) {
    int idx = blockIdx.x*blockDim.x + threadIdx.x;   // B*T*N*H
    int h = idx & 127;
    int n = (idx >> 7) & 1023;
    int t = (idx >> 17) & 15;
    int b = idx >> 21;
    size_t ib = ((size_t)(b*TT + t)*NN + n)*2;
    float v = in[ib]*Win[h] + in[ib+1]*Win[128+h] + bin[h] + spat[n*128+h] + temp[n*16+t];
    g_x[idx] = v;
}

// ---------------- assemble fs for segment iter, zero stats --------------------
__global__ void k_fs(int iter, int left) {
    int idx = blockIdx.x*blockDim.x + threadIdx.x;   // B*4*N*H
    int h = idx & 127;
    int n = (idx >> 7) & 1023;
    int s = (idx >> 17) & 3;
    int b = idx >> 19;
    float val;
    if (iter > 0 && s == 0) {
        val = g_last[((size_t)b*NN + n)*128 + h];
    } else {
        int t = left + s - (iter > 0 ? 1 : 0);
        val = g_x[(((size_t)b*TT + t)*NN + n)*128 + h];
    }
    g_fs[idx] = val;
    if (idx < 2*BB) g_stats[idx] = 0.f;
}

// ---------------- SGEMM: C[M,128] = A[M,128] @ W[128,128] ---------------------
// 128x128 tile per block, 256 threads, 8x8 microtile, BK=16
__global__ __launch_bounds__(256) void k_gemm(int a_sel, const float* __restrict__ W) {
    const float* __restrict__ A = a_sel ? g_h0 : g_fs;
    float* __restrict__ C = g_feat;
    __shared__ float As[16][132];
    __shared__ float Bs[16][128];
    int tid = threadIdx.x;
    int block_row = blockIdx.x * 128;
    int tx = tid & 15, ty = tid >> 4;
    float acc[8][8];
    #pragma unroll
    for (int i = 0; i < 8; i++)
        #pragma unroll
        for (int j = 0; j < 8; j++) acc[i][j] = 0.f;

    for (int k0 = 0; k0 < 128; k0 += 16) {
        #pragma unroll
        for (int i = 0; i < 2; i++) {
            int f4 = tid*2 + i;            // 0..511
            int r = f4 >> 2;               // 0..127
            int c4 = (f4 & 3) * 4;
            float4 v = *(const float4*)&A[(size_t)(block_row + r)*128 + k0 + c4];
            As[c4+0][r] = v.x; As[c4+1][r] = v.y; As[c4+2][r] = v.z; As[c4+3][r] = v.w;
        }
        #pragma unroll
        for (int i = 0; i < 2; i++) {
            int f4 = tid*2 + i;
            int r = f4 >> 5;               // 0..15
            int c4 = (f4 & 31) * 4;
            *(float4*)&Bs[r][c4] = *(const float4*)&W[(size_t)(k0 + r)*128 + c4];
        }
        __syncthreads();
        #pragma unroll
        for (int k = 0; k < 16; k++) {
            float ar[8], br[8];
            #pragma unroll
            for (int i = 0; i < 8; i++) ar[i] = As[k][ty*8+i];
            #pragma unroll
            for (int i = 0; i < 8; i++) br[i] = Bs[k][tx*8+i];
            #pragma unroll
            for (int i = 0; i < 8; i++)
                #pragma unroll
                for (int j = 0; j < 8; j++) acc[i][j] += ar[i]*br[j];
        }
        __syncthreads();
    }
    #pragma unroll
    for (int i = 0; i < 8; i++) {
        size_t r = (size_t)(block_row + ty*8 + i)*128 + tx*8;
        float4 v0 = {acc[i][0], acc[i][1], acc[i][2], acc[i][3]};
        float4 v1 = {acc[i][4], acc[i][5], acc[i][6], acc[i][7]};
        *(float4*)&C[r]   = v0;
        *(float4*)&C[r+4] = v1;
    }
}

// ---------------- el/er: per (row, head) dot over HD=16 -----------------------
__global__ void k_eler(const float* __restrict__ al, const float* __restrict__ ar) {
    int idx = blockIdx.x*blockDim.x + threadIdx.x;   // B*NT*8
    if (idx >= BB*NT*NHEADS) return;
    int head = idx & 7;
    size_t row = idx >> 3;
    const float* f = &g_feat[row*128 + head*16];
    float sl = 0.f, sr = 0.f;
    #pragma unroll
    for (int k = 0; k < 16; k++) {
        float fv = f[k];
        sl += fv * al[head*16+k];
        sr += fv * ar[head*16+k];
    }
    g_el[idx] = sl;
    g_er[idx] = sr;
}

// ---------------- attention softmax per (b, node, head) -----------------------
__global__ void k_attn(int E) {
    int idx = blockIdx.x*blockDim.x + threadIdx.x;   // B*NT*8
    if (idx >= BB*NT*NHEADS) return;
    int head = idx & 7;
    int v = (idx >> 3) & (NT-1);
    int b = idx >> 15;
    int o0 = g_off[v];
    int d = g_deg[v]; if (d > MAXDEG) d = MAXDEG;
    float erv = g_er[((size_t)b*NT + v)*8 + head];
    float ereg[MAXDEG];
    float m = -1e30f;
    #pragma unroll
    for (int j = 0; j < MAXDEG; j++) {
        if (j < d) {
            int s = g_srcs[o0+j];
            float e = g_el[((size_t)b*NT + s)*8 + head] + erv;
            e = e > 0.f ? e : LRELU_SLOPE*e;
            ereg[j] = e;
            m = fmaxf(m, e);
        }
    }
    float ssum = 0.f;
    #pragma unroll
    for (int j = 0; j < MAXDEG; j++) {
        if (j < d) { float w = expf(ereg[j]-m); ereg[j] = w; ssum += w; }
    }
    float rinv = 1.0f/ssum;
    size_t abase = ((size_t)b*E + o0)*8 + head;
    #pragma unroll
    for (int j = 0; j < MAXDEG; j++) {
        if (j < d) g_alpha[abase + (size_t)j*8] = ereg[j]*rinv;
    }
}

// ---------------- aggregation: warp per (b, node), lane = 4 dims --------------
// out = activate(sum_e alpha_e * feat[src] + bias) [+ residual]
__global__ void k_agg(int layer, const float* __restrict__ bias, int E) {
    int warp = (blockIdx.x * blockDim.x + threadIdx.x) >> 5;
    int lane = threadIdx.x & 31;
    if (warp >= BB*NT) return;
    int v = warp & (NT-1);
    int b = warp >> 12;
    int o0 = g_off[v];
    int d = g_deg[v]; if (d > MAXDEG) d = MAXDEG;
    int sreg[MAXDEG];
    float areg[MAXDEG];
    #pragma unroll
    for (int j = 0; j < MAXDEG; j++) {
        if (j < d) sreg[j] = g_srcs[o0+j];
    }
    size_t abase = ((size_t)b*E + o0)*8;
    #pragma unroll
    for (int j = 0; j < MAXDEG; j++) {
        if (j < d && lane < 8) areg[j] = g_alpha[abase + (size_t)j*8 + lane];
        else areg[j] = 0.f;
    }
    float4 acc = make_float4(0.f, 0.f, 0.f, 0.f);
    size_t fb = (size_t)b*NT;
    #pragma unroll
    for (int j = 0; j < MAXDEG; j++) {
        if (j < d) {
            float a = __shfl_sync(0xffffffffu, areg[j], lane >> 2);
            const float4 f = *(const float4*)&g_feat[(fb + sreg[j])*128 + lane*4];
            acc.x += a*f.x; acc.y += a*f.y; acc.z += a*f.z; acc.w += a*f.w;
        }
    }
    float4 bb = *(const float4*)&bias[lane*4];
    acc.x += bb.x; acc.y += bb.y; acc.z += bb.z; acc.w += bb.w;
    size_t r = (size_t)warp*128 + lane*4;
    if (layer == 0) {
        acc.x = acc.x > 0.f ? acc.x : expm1f(acc.x);
        acc.y = acc.y > 0.f ? acc.y : expm1f(acc.y);
        acc.z = acc.z > 0.f ? acc.z : expm1f(acc.z);
        acc.w = acc.w > 0.f ? acc.w : expm1f(acc.w);
        *(float4*)&g_h0[r] = acc;
    } else {
        const float4 rv = *(const float4*)&g_fs[r];
        acc.x += rv.x; acc.y += rv.y; acc.z += rv.z; acc.w += rv.w;
        *(float4*)&g_h1[r] = acc;
    }
}

// ---------------- attention pooling over the 4 snapshots + stats --------------
__global__ void k_pool(const float* __restrict__ q) {
    int bn = blockIdx.x;           // b*N + n
    int b = bn >> 10;
    int n = bn & 1023;
    int tid = threadIdx.x;         // 128
    __shared__ float sbuf[128];
    float qv = q[n*128 + tid];
    float xs[4], sc[4];
    #pragma unroll
    for (int t = 0; t < 4; t++)
        xs[t] = g_h1[((size_t)b*NT + t*NN + n)*128 + tid];
    #pragma unroll
    for (int t = 0; t < 4; t++) {
        sbuf[tid] = xs[t]*qv; __syncthreads();
        for (int s = 64; s > 0; s >>= 1) {
            if (tid < s) sbuf[tid] += sbuf[tid+s];
            __syncthreads();
        }
        sc[t] = sbuf[0];
        __syncthreads();
    }
    float m = fmaxf(fmaxf(sc[0], sc[1]), fmaxf(sc[2], sc[3]));
    float e0 = expf(sc[0]-m), e1 = expf(sc[1]-m), e2 = expf(sc[2]-m), e3 = expf(sc[3]-m);
    float rs = 1.0f/(e0+e1+e2+e3);
    float lastv = (e0*xs[0] + e1*xs[1] + e2*xs[2] + e3*xs[3])*rs;
    g_last[(size_t)bn*128 + tid] = lastv;
    // per-batch stats
    sbuf[tid] = lastv; __syncthreads();
    for (int s = 64; s > 0; s >>= 1) { if (tid < s) sbuf[tid] += sbuf[tid+s]; __syncthreads(); }
    if (tid == 0) atomicAdd(&g_stats[b*2], sbuf[0]);
    __syncthreads();
    sbuf[tid] = lastv*lastv; __syncthreads();
    for (int s = 64; s > 0; s >>= 1) { if (tid < s) sbuf[tid] += sbuf[tid+s]; __syncthreads(); }
    if (tid == 0) atomicAdd(&g_stats[b*2+1], sbuf[0]);
}

// ---------------- per-batch layernorm of g_last -------------------------------
__global__ void k_norm() {
    int idx = blockIdx.x*blockDim.x + threadIdx.x;   // B*N*H
    int b = idx >> 17;                                // N*H = 131072
    const float inv = 1.0f/(float)(NN*HH);
    float mu = g_stats[b*2]*inv;
    float var = g_stats[b*2+1]*inv - mu*mu;
    g_last[idx] = (g_last[idx] - mu) * rsqrtf(var + 1e-5f);
}

// ---------------- output head ------------------------------------------------
__global__ void k_out(const float* __restrict__ w1, const float* __restrict__ b1,
                      const float* __restrict__ w2, const float* __restrict__ b2,
                      float* __restrict__ out) {
    int bn = blockIdx.x;           // b*N + n
    int b = bn >> 10;
    int n = bn & 1023;
    int tid = threadIdx.x;         // 128
    __shared__ float sbuf[128];
    float lv = g_last[(size_t)bn*128 + tid];
    float w2v = w2[tid];
    for (int s = 0; s < 12; s++) {
        float t = lv*w1[s] + b1[s];
        t = t > 0.f ? t : 0.f;
        sbuf[tid] = t*w2v; __syncthreads();
        for (int k = 64; k > 0; k >>= 1) {
            if (tid < k) sbuf[tid] += sbuf[tid+k];
            __syncthreads();
        }
        if (tid == 0) out[((size_t)b*12 + s)*NN + n] = sbuf[0] + b2[0];
        __syncthreads();
    }
}

// =============================================================================
extern "C" void kernel_launch(void* const* d_in, const int* in_sizes, int n_in,
                              void* d_out, int out_size) {
    const float* inputs   = (const float*)d_in[0];
    const float* W_in     = (const float*)d_in[1];
    const float* b_in     = (const float*)d_in[2];
    const float* spat     = (const float*)d_in[3];
    const float* temp     = (const float*)d_in[4];
    const float* gat_w0   = (const float*)d_in[5];
    const float* gat_al0  = (const float*)d_in[6];
    const float* gat_ar0  = (const float*)d_in[7];
    const float* gat_b0   = (const float*)d_in[8];
    const float* gat_w1   = (const float*)d_in[9];
    const float* gat_al1  = (const float*)d_in[10];
    const float* gat_ar1  = (const float*)d_in[11];
    const float* gat_b1   = (const float*)d_in[12];
    const float* agg_q    = (const float*)d_in[13];
    const float* w_out1   = (const float*)d_in[14];
    const float* b_out1   = (const float*)d_in[15];
    const float* w_out2   = (const float*)d_in[16];
    const float* b_out2   = (const float*)d_in[17];
    const int*   esrc     = (const int*)d_in[18];
    const int*   edst     = (const int*)d_in[19];
    int E = in_sizes[18];

    // CSR build (same inputs every call -> deterministic; per-node sort fixes order)
    k_zero<<<(NT+255)/256, 256>>>();
    k_count<<<(E+255)/256, 256>>>(edst, E);
    k_scan<<<1, 1024>>>();
    k_fill<<<(E+255)/256, 256>>>(edst, E);
    k_sort<<<(NT+127)/128, 128>>>(esrc);

    // x
    k_x<<<(BB*TT*NN*HH)/256, 256>>>(inputs, W_in, b_in, spat, temp);

    const int lefts[5] = {0, 4, 7, 10, 13};
    for (int it = 0; it < 5; it++) {
        k_fs<<<(BB*SNP*NN*HH)/256, 256>>>(it, lefts[it]);
        // GAT layer 0
        k_gemm<<<(BB*NT)/128, 256>>>(0, gat_w0);
        k_eler<<<(BB*NT*NHEADS+255)/256, 256>>>(gat_al0, gat_ar0);
        k_attn<<<(BB*NT*NHEADS+255)/256, 256>>>(E);
        k_agg<<<(BB*NT*32)/256, 256>>>(0, gat_b0, E);
        // GAT layer 1
        k_gemm<<<(BB*NT)/128, 256>>>(1, gat_w1);
        k_eler<<<(BB*NT*NHEADS+255)/256, 256>>>(gat_al1, gat_ar1);
        k_attn<<<(BB*NT*NHEADS+255)/256, 256>>>(E);
        k_agg<<<(BB*NT*32)/256, 256>>>(1, gat_b1, E);
        // pool + layernorm
        k_pool<<<BB*NN, 128>>>(agg_q);
        k_norm<<<(BB*NN*HH)/256, 256>>>();
    }

    k_out<<<BB*NN, 128>>>(w_out1, b_out1, w_out2, b_out2, (float*)d_out);
}